// round 2
// baseline (speedup 1.0000x reference)
#include <cuda_runtime.h>
#include <cstdint>

// Problem constants
// x:      (8, 64, 96, 96)  fp32
// offset: (8, 18, 96, 96)  fp32   (k*2+0 = dy, k*2+1 = dx)
// x2:     (8, 64, 96, 96)  fp32
// weight: (64, 64, 3, 3)   fp32
// bias:   (64,)            fp32
// out:    (8, 64, 96, 96)  fp32 = clip(deform_conv(x,offset,W)+bias+x2, 0, 6)

typedef unsigned long long ull;

#define HW      9216            // 96*96
#define SP      34              // S row pitch (floats): odd*2 -> bank-spread, 136B = 8B aligned rows
#define SFLOATS (576 * SP)
#define WCFLOAT (64 * 64)
#define SMEM_BYTES ((SFLOATS + WCFLOAT) * 4)

// Scratch (allocation-free rule: __device__ globals)
__device__ float g_xT[8 * 96 * 96 * 64];   // NHWC transposed input, 18.9 MB
__device__ float g_Wt[576 * 64];           // Wt[i=k*64+c][oc] = weight[oc][c][k]

__device__ __forceinline__ ull fma2(ull a, ull b, ull c) {
    ull d;
    asm("fma.rn.f32x2 %0, %1, %2, %3;" : "=l"(d) : "l"(a), "l"(b), "l"(c));
    return d;
}
__device__ __forceinline__ ull pack2(float lo, float hi) {
    ull d;
    asm("mov.b64 %0, {%1, %2};" : "=l"(d) : "f"(lo), "f"(hi));
    return d;
}
__device__ __forceinline__ void unpack2(ull v, float& lo, float& hi) {
    asm("mov.b64 {%0, %1}, %2;" : "=f"(lo), "=f"(hi) : "l"(v));
}

// ---------------------------------------------------------------------------
// NCHW -> NHWC transpose of x (smem-tiled, coalesced both sides)
// grid (3, 2, 768): x = w-tile, y = c-tile, z = b*96 + h
// ---------------------------------------------------------------------------
__global__ void transpose_x_kernel(const float* __restrict__ x) {
    __shared__ float tile[32][33];
    int bh = blockIdx.z;
    int c0 = blockIdx.y * 32;
    int w0 = blockIdx.x * 32;
    int b = bh / 96, h = bh - b * 96;
    int tx = threadIdx.x, ty = threadIdx.y;
    // read x[b][c0+ty][h][w0+tx]  (coalesced in w)
    tile[ty][tx] = x[(((size_t)b * 64 + c0 + ty) * 96 + h) * 96 + w0 + tx];
    __syncthreads();
    // write xT[b][h][w0+ty][c0+tx] (coalesced in c)
    g_xT[(((size_t)b * 96 + h) * 96 + (w0 + ty)) * 64 + c0 + tx] = tile[tx][ty];
}

// weight[oc][c][kh][kw] -> Wt[k*64+c][oc]
__global__ void transpose_w_kernel(const float* __restrict__ w) {
    int o = blockIdx.x * 256 + threadIdx.x;
    if (o < 576 * 64) {
        int i = o >> 6, oc = o & 63;
        int k = i >> 6, c = i & 63;
        g_Wt[o] = w[(oc * 64 + c) * 9 + k];
    }
}

// ---------------------------------------------------------------------------
// Main fused kernel: 1 block = 32 output pixels (one batch), 128 threads.
// Phase 1: bilinear im2col into smem S[576][32] (lanes = channel pairs).
// Phase 2: f32x2-packed register-tiled GEMM  out[32px][64oc] = S^T @ Wt.
// Phase 3: + bias + x2, clip to [0,6], store.
// ---------------------------------------------------------------------------
__global__ __launch_bounds__(128, 2) void deform_main_kernel(
    const float* __restrict__ off,
    const float* __restrict__ x2,
    const float* __restrict__ bias,
    float* __restrict__ out)
{
    extern __shared__ float smem[];
    float* S  = smem;              // [576][SP]
    float* Wc = smem + SFLOATS;    // [64][64] weight chunk

    const int tid  = threadIdx.x;
    const int lane = tid & 31;
    const int wid  = tid >> 5;

    const int blk = blockIdx.x;
    const int b   = blk / 288;            // 288 tiles per batch image
    const int pb  = (blk - b * 288) * 32; // first pixel (ho*96+wo) of tile

    const float* xTb  = g_xT + (size_t)b * (HW * 64);
    const float* offb = off + (size_t)b * (18 * HW);

    // ---------- Phase 1: sampling (288 tasks = 9 taps x 32 pixels) ----------
    for (int t = wid; t < 288; t += 4) {
        int k  = t >> 5;          // tap 0..8
        int pl = t & 31;          // pixel within tile
        int p  = pb + pl;
        int ho = p / 96;
        int wo = p - ho * 96;

        float oy = __ldg(offb + (size_t)(2 * k) * HW + p);
        float ox = __ldg(offb + (size_t)(2 * k + 1) * HW + p);
        int ki = k / 3;
        int kj = k - ki * 3;
        float y = (float)(ho - 1 + ki) + oy;
        float x = (float)(wo - 1 + kj) + ox;

        float y0f = floorf(y), x0f = floorf(x);
        float wy1 = y - y0f,   wx1 = x - x0f;
        float wy0 = 1.0f - wy1, wx0 = 1.0f - wx1;
        int y0 = (int)y0f, x0 = (int)x0f;

        bool vy0 = (y0 >= 0) && (y0 <= 95);
        bool vy1 = (y0 >= -1) && (y0 <= 94);
        bool vx0 = (x0 >= 0) && (x0 <= 95);
        bool vx1 = (x0 >= -1) && (x0 <= 94);
        int yc0 = min(max(y0, 0), 95),     yc1 = min(max(y0 + 1, 0), 95);
        int xc0 = min(max(x0, 0), 95),     xc1 = min(max(x0 + 1, 0), 95);

        float w00 = (vy0 && vx0) ? wy0 * wx0 : 0.0f;
        float w01 = (vy0 && vx1) ? wy0 * wx1 : 0.0f;
        float w10 = (vy1 && vx0) ? wy1 * wx0 : 0.0f;
        float w11 = (vy1 && vx1) ? wy1 * wx1 : 0.0f;

        int c2 = lane * 2;  // lane handles channels c2, c2+1 (coalesced gathers)
        float2 v00 = *(const float2*)(xTb + ((size_t)(yc0 * 96 + xc0) << 6) + c2);
        float2 v01 = *(const float2*)(xTb + ((size_t)(yc0 * 96 + xc1) << 6) + c2);
        float2 v10 = *(const float2*)(xTb + ((size_t)(yc1 * 96 + xc0) << 6) + c2);
        float2 v11 = *(const float2*)(xTb + ((size_t)(yc1 * 96 + xc1) << 6) + c2);

        float s0 = w00 * v00.x + w01 * v01.x + w10 * v10.x + w11 * v11.x;
        float s1 = w00 * v00.y + w01 * v01.y + w10 * v10.y + w11 * v11.y;

        int i = k * 64 + c2;
        S[i * SP + pl]       = s0;
        S[(i + 1) * SP + pl] = s1;
    }

    // ---------- Phase 2: GEMM ----------
    // thread (pg, ocg): pg = pixel-group (2 pixel-pairs = 4 px), ocg = 4 output channels
    const int pg  = tid & 7;    // 0..7  -> pixels 4*pg .. 4*pg+3
    const int ocg = tid >> 3;   // 0..15 -> oc 4*ocg .. 4*ocg+3

    ull acc[2][4];
    #pragma unroll
    for (int a = 0; a < 2; a++)
        #pragma unroll
        for (int m = 0; m < 4; m++) acc[a][m] = 0ULL;  // two packed 0.0f

    const float* Sbase = S + 4 * pg;

    for (int ic0 = 0; ic0 < 576; ic0 += 64) {
        __syncthreads();   // also covers Phase-1 -> Phase-2 on first pass
        #pragma unroll
        for (int j = 0; j < 32; j++)
            Wc[j * 128 + tid] = g_Wt[(size_t)ic0 * 64 + j * 128 + tid];
        __syncthreads();

        #pragma unroll
        for (int ii = 0; ii < 64; ii++) {
            const float* sr = Sbase + (ic0 + ii) * SP;
            ull a0 = *(const ull*)(sr);        // pixels 4pg, 4pg+1
            ull a1 = *(const ull*)(sr + 2);    // pixels 4pg+2, 4pg+3
            float4 w4 = *(const float4*)(Wc + ii * 64 + 4 * ocg);
            ull w0 = pack2(w4.x, w4.x);
            ull w1 = pack2(w4.y, w4.y);
            ull w2 = pack2(w4.z, w4.z);
            ull w3 = pack2(w4.w, w4.w);
            acc[0][0] = fma2(a0, w0, acc[0][0]);
            acc[1][0] = fma2(a1, w0, acc[1][0]);
            acc[0][1] = fma2(a0, w1, acc[0][1]);
            acc[1][1] = fma2(a1, w1, acc[1][1]);
            acc[0][2] = fma2(a0, w2, acc[0][2]);
            acc[1][2] = fma2(a1, w2, acc[1][2]);
            acc[0][3] = fma2(a0, w3, acc[0][3]);
            acc[1][3] = fma2(a1, w3, acc[1][3]);
        }
    }

    // ---------- Phase 3: epilogue ----------
    #pragma unroll
    for (int m = 0; m < 4; m++) {
        int oc = ocg * 4 + m;
        float bv = __ldg(bias + oc);
        size_t obase = ((size_t)b * 64 + oc) * HW + pb + 4 * pg;
        #pragma unroll
        for (int pr = 0; pr < 2; pr++) {
            float lo, hi;
            unpack2(acc[pr][m], lo, hi);
            float2 xv = *(const float2*)(x2 + obase + 2 * pr);
            lo = fminf(fmaxf(lo + bv + xv.x, 0.0f), 6.0f);
            hi = fminf(fmaxf(hi + bv + xv.y, 0.0f), 6.0f);
            *(float2*)(out + obase + 2 * pr) = make_float2(lo, hi);
        }
    }
}

extern "C" void kernel_launch(void* const* d_in, const int* in_sizes, int n_in,
                              void* d_out, int out_size) {
    const float* x      = (const float*)d_in[0];
    const float* offset = (const float*)d_in[1];
    const float* x2     = (const float*)d_in[2];
    const float* weight = (const float*)d_in[3];
    const float* bias   = (const float*)d_in[4];
    float* out = (float*)d_out;
    (void)in_sizes; (void)n_in; (void)out_size;

    cudaFuncSetAttribute(deform_main_kernel,
                         cudaFuncAttributeMaxDynamicSharedMemorySize, SMEM_BYTES);

    transpose_x_kernel<<<dim3(3, 2, 768), dim3(32, 32)>>>(x);
    transpose_w_kernel<<<144, 256>>>(weight);
    deform_main_kernel<<<2304, 128, SMEM_BYTES>>>(offset, x2, bias, out);
}

// round 4
// speedup vs baseline: 1.4224x; 1.4224x over previous
#include <cuda_runtime.h>
#include <cstdint>

// x: (8,64,96,96) f32 | offset: (8,18,96,96) | x2: (8,64,96,96)
// weight: (64,64,3,3) | bias: (64,) | out = clip(dcn(x,off,W)+b+x2, 0, 6)

typedef unsigned long long ull;

#define HW   9216
#define SCHP 130                          // S chunk row pitch (floats): 2-way STS, 8B-aligned rows
#define S_CHUNK_FLOATS (64 * SCHP)        // one tap: 64 ch x 128 px (+pad)
#define WC_FLOATS      (64 * 64)
#define SMEM_FLOATS    (2 * S_CHUNK_FLOATS + 2 * WC_FLOATS)
#define SMEM_BYTES     (SMEM_FLOATS * 4)  // 99,328 B -> 2 blocks/SM

__device__ float g_xT[8 * 96 * 96 * 64];  // NHWC input
__device__ float g_Wt[576 * 64];          // Wt[k*64+c][oc]

__device__ __forceinline__ ull fma2(ull a, ull b, ull c) {
    ull d; asm("fma.rn.f32x2 %0, %1, %2, %3;" : "=l"(d) : "l"(a), "l"(b), "l"(c));
    return d;
}
__device__ __forceinline__ ull pack2(float lo, float hi) {
    ull d; asm("mov.b64 %0, {%1, %2};" : "=l"(d) : "f"(lo), "f"(hi));
    return d;
}
__device__ __forceinline__ void unpack2(ull v, float& lo, float& hi) {
    asm("mov.b64 {%0, %1}, %2;" : "=f"(lo), "=f"(hi) : "l"(v));
}

// ---------------------------------------------------------------------------
// NCHW -> NHWC transpose. 128 threads per block.
// Read:  c = (tid>>5) + 4i (0..31), w = tid&31     (coalesced in w)
// Write: w = tid>>2 (0..31), channel quad q = (tid&3)+4i (0..7), float4 store
// grid (3, 2, 768)
// ---------------------------------------------------------------------------
__global__ void transpose_x_kernel(const float* __restrict__ x) {
    __shared__ float tile[32][33];
    int bh = blockIdx.z, c0 = blockIdx.y * 32, w0 = blockIdx.x * 32;
    int b = bh / 96, h = bh - b * 96;
    int tid = threadIdx.x;
    int tx = tid & 31, ty = tid >> 5;
    #pragma unroll
    for (int i = 0; i < 8; i++) {
        int c = ty + 4 * i;
        tile[c][tx] = x[(((size_t)b * 64 + c0 + c) * 96 + h) * 96 + w0 + tx];
    }
    __syncthreads();
    int wi = tid >> 2;
    #pragma unroll
    for (int i = 0; i < 2; i++) {
        int q = (tid & 3) + 4 * i;       // channel quad 0..7
        float4 v = make_float4(tile[4 * q][wi], tile[4 * q + 1][wi],
                               tile[4 * q + 2][wi], tile[4 * q + 3][wi]);
        *(float4*)&g_xT[(((size_t)b * 96 + h) * 96 + (w0 + wi)) * 64 + c0 + 4 * q] = v;
    }
}

// weight[oc][c][k] -> Wt[k*64+c][oc]
__global__ void transpose_w_kernel(const float* __restrict__ w) {
    int o = blockIdx.x * 256 + threadIdx.x;
    if (o < 576 * 64) {
        int i = o >> 6, oc = o & 63;
        int k = i >> 6, c = i & 63;
        g_Wt[o] = w[(oc * 64 + c) * 9 + k];
    }
}

// ---------------------------------------------------------------------------
// Main kernel: block = 128 px x 64 oc, 128 threads, thread tile 8px x 8oc.
// Per tap (K-chunk of 64): sample S[64ch][128px] (double-buffered) + Wc chunk,
// then f32x2 GEMM. Epilogue: +bias +x2, clip [0,6].
// ---------------------------------------------------------------------------
__global__ __launch_bounds__(128, 2) void deform_main_kernel(
    const float* __restrict__ off,
    const float* __restrict__ x2,
    const float* __restrict__ bias,
    float* __restrict__ out)
{
    extern __shared__ float smem[];
    float* Sm = smem;                         // [2][64][SCHP]
    float* Wm = smem + 2 * S_CHUNK_FLOATS;    // [2][64][64] (bank-swizzled rows)

    const int tid  = threadIdx.x;
    const int lane = tid & 31;
    const int wid  = tid >> 5;
    const int pg   = tid >> 3;    // 0..15 -> pixels pg*8 .. pg*8+7
    const int og   = tid & 7;     // 0..7  -> oc og*8 .. og*8+7

    const int blk = blockIdx.x;
    const int b   = blk / 72;
    const int pb  = (blk - b * 72) * 128;

    const float* xTb  = g_xT + (size_t)b * (HW * 64);
    const float* offb = off + (size_t)b * (18 * HW);

    ull acc[4][8];
    #pragma unroll
    for (int p = 0; p < 4; p++)
        #pragma unroll
        for (int m = 0; m < 8; m++) acc[p][m] = 0ULL;

    // ---- sampling of one tap into Sbuf[64][SCHP] ----
    auto sample = [&](int k, float* Sbuf) {
        int ki = k / 3, kj = k - ki * 3;
        const float* offy = offb + (size_t)(2 * k) * HW;
        const float* offx = offy + HW;
        #pragma unroll 2
        for (int i = 0; i < 32; i++) {
            int t = wid * 32 + i;            // px within tile
            int p = pb + t;
            int ho = p / 96;
            int wo = p - ho * 96;

            float oy = __ldg(offy + p);
            float ox = __ldg(offx + p);
            float y = (float)(ho - 1 + ki) + oy;
            float x = (float)(wo - 1 + kj) + ox;

            float y0f = floorf(y), x0f = floorf(x);
            float wy1 = y - y0f, wx1 = x - x0f;
            float wy0 = 1.0f - wy1, wx0 = 1.0f - wx1;
            int y0 = (int)y0f, x0 = (int)x0f;

            bool vy0 = (y0 >= 0) && (y0 <= 95);
            bool vy1 = (y0 >= -1) && (y0 <= 94);
            bool vx0 = (x0 >= 0) && (x0 <= 95);
            bool vx1 = (x0 >= -1) && (x0 <= 94);
            int yc0 = min(max(y0, 0), 95), yc1 = min(max(y0 + 1, 0), 95);
            int xc0 = min(max(x0, 0), 95), xc1 = min(max(x0 + 1, 0), 95);

            float w00 = (vy0 && vx0) ? wy0 * wx0 : 0.0f;
            float w01 = (vy0 && vx1) ? wy0 * wx1 : 0.0f;
            float w10 = (vy1 && vx0) ? wy1 * wx0 : 0.0f;
            float w11 = (vy1 && vx1) ? wy1 * wx1 : 0.0f;

            const float* b00 = xTb + ((size_t)(yc0 * 96 + xc0) << 6);
            const float* b01 = xTb + ((size_t)(yc0 * 96 + xc1) << 6);
            const float* b10 = xTb + ((size_t)(yc1 * 96 + xc0) << 6);
            const float* b11 = xTb + ((size_t)(yc1 * 96 + xc1) << 6);

            // lane owns channels lane and lane+32 (coalesced 128B gathers)
            float a00 = __ldg(b00 + lane), c00 = __ldg(b00 + lane + 32);
            float a01 = __ldg(b01 + lane), c01 = __ldg(b01 + lane + 32);
            float a10 = __ldg(b10 + lane), c10 = __ldg(b10 + lane + 32);
            float a11 = __ldg(b11 + lane), c11 = __ldg(b11 + lane + 32);

            float sa = w00 * a00 + w01 * a01 + w10 * a10 + w11 * a11;
            float sc = w00 * c00 + w01 * c01 + w10 * c10 + w11 * c11;

            Sbuf[lane * SCHP + t]        = sa;   // 2-way bank conflict only
            Sbuf[(lane + 32) * SCHP + t] = sc;
        }
    };

    // ---- stage one 64x64 weight chunk (bank-swizzled) ----
    auto fillW = [&](int k, float* Wbuf) {
        #pragma unroll
        for (int j = 0; j < 8; j++) {
            int e4  = tid + 128 * j;       // float4 index, 0..1023
            int ii  = e4 >> 4;             // 0..63
            int oc4 = (e4 & 15) << 2;      // 0,4,...,60
            float4 v = *(const float4*)&g_Wt[(size_t)(k * 64 + ii) * 64 + oc4];
            int g = oc4 >> 3;              // oc group 0..7
            int half = (oc4 >> 2) & 1;     // low/high half of group
            int s = (g >> 2) & 1;          // swizzle bit
            int pos = g * 8 + ((s ^ half) ? 4 : 0);
            *(float4*)&Wbuf[ii * 64 + pos] = v;
        }
    };

#define FMAG(m, wv) { ull wd = pack2((wv), (wv));              \
        acc[0][m] = fma2(a0, wd, acc[0][m]);                   \
        acc[1][m] = fma2(a1, wd, acc[1][m]);                   \
        acc[2][m] = fma2(a2, wd, acc[2][m]);                   \
        acc[3][m] = fma2(a3, wd, acc[3][m]); }

    auto gemm = [&](const float* Sbuf, const float* Wbuf) {
        const float* Sb = Sbuf + pg * 8;
        int s = (og >> 2) & 1;
        const float* wAp = Wbuf + og * 8 + s * 4;
        const float* wBp = Wbuf + og * 8 + (s ^ 1) * 4;
        #pragma unroll 8
        for (int ii = 0; ii < 64; ii++) {
            const float* sr = Sb + ii * SCHP;
            ull a0 = *(const ull*)(sr);
            ull a1 = *(const ull*)(sr + 2);
            ull a2 = *(const ull*)(sr + 4);
            ull a3 = *(const ull*)(sr + 6);
            float4 wA = *(const float4*)(wAp + ii * 64);  // oc og*8+0..3
            float4 wB = *(const float4*)(wBp + ii * 64);  // oc og*8+4..7
            FMAG(0, wA.x); FMAG(1, wA.y); FMAG(2, wA.z); FMAG(3, wA.w);
            FMAG(4, wB.x); FMAG(5, wB.y); FMAG(6, wB.z); FMAG(7, wB.w);
        }
    };
#undef FMAG

    // ---- pipelined main loop over 9 taps ----
    sample(0, Sm);
    fillW(0, Wm);
    __syncthreads();
    for (int c = 0; c < 9; c++) {
        int buf = c & 1, nb = buf ^ 1;
        if (c < 8) {
            sample(c + 1, Sm + nb * S_CHUNK_FLOATS);
            fillW(c + 1, Wm + nb * WC_FLOATS);
        }
        gemm(Sm + buf * S_CHUNK_FLOATS, Wm + buf * WC_FLOATS);
        __syncthreads();
    }

    // ---- epilogue: + bias + x2, clip [0,6] ----
    #pragma unroll
    for (int m = 0; m < 8; m++) {
        int oc = og * 8 + m;
        float bv = __ldg(bias + oc);
        size_t base = ((size_t)(b * 64 + oc)) * HW + pb + pg * 8;
        float4 xa = *(const float4*)(x2 + base);
        float4 xb = *(const float4*)(x2 + base + 4);
        float p0, p1, p2, p3, p4, p5, p6, p7;
        unpack2(acc[0][m], p0, p1);
        unpack2(acc[1][m], p2, p3);
        unpack2(acc[2][m], p4, p5);
        unpack2(acc[3][m], p6, p7);
        float4 ra, rb;
        ra.x = fminf(fmaxf(p0 + bv + xa.x, 0.0f), 6.0f);
        ra.y = fminf(fmaxf(p1 + bv + xa.y, 0.0f), 6.0f);
        ra.z = fminf(fmaxf(p2 + bv + xa.z, 0.0f), 6.0f);
        ra.w = fminf(fmaxf(p3 + bv + xa.w, 0.0f), 6.0f);
        rb.x = fminf(fmaxf(p4 + bv + xb.x, 0.0f), 6.0f);
        rb.y = fminf(fmaxf(p5 + bv + xb.y, 0.0f), 6.0f);
        rb.z = fminf(fmaxf(p6 + bv + xb.z, 0.0f), 6.0f);
        rb.w = fminf(fmaxf(p7 + bv + xb.w, 0.0f), 6.0f);
        *(float4*)(out + base)     = ra;
        *(float4*)(out + base + 4) = rb;
    }
}

extern "C" void kernel_launch(void* const* d_in, const int* in_sizes, int n_in,
                              void* d_out, int out_size) {
    const float* x      = (const float*)d_in[0];
    const float* offset = (const float*)d_in[1];
    const float* x2     = (const float*)d_in[2];
    const float* weight = (const float*)d_in[3];
    const float* bias   = (const float*)d_in[4];
    float* out = (float*)d_out;
    (void)in_sizes; (void)n_in; (void)out_size;

    cudaFuncSetAttribute(deform_main_kernel,
                         cudaFuncAttributeMaxDynamicSharedMemorySize, SMEM_BYTES);

    transpose_x_kernel<<<dim3(3, 2, 768), 128>>>(x);
    transpose_w_kernel<<<144, 256>>>(weight);
    deform_main_kernel<<<576, 128, SMEM_BYTES>>>(offset, x2, bias, out);
}

// round 6
// speedup vs baseline: 2.4211x; 1.7021x over previous
#include <cuda_runtime.h>
#include <cuda_bf16.h>
#include <cstdint>

typedef unsigned int u32;
typedef unsigned long long ull;

#define HW 9216

// ---- dynamic smem layout (bytes) ----
#define S_TILE 16384                       // [128 px][64 ic] bf16, SW128 rows (128B)
#define W_TILE 8192                        // [64 oc][64 ic] bf16, SW128 rows (128B)
#define SM_SHI 0
#define SM_SLO S_TILE
#define SM_WHI (2 * S_TILE)
#define SM_WLO (2 * S_TILE + W_TILE)
#define SMEM_BYTES (2 * S_TILE + 2 * W_TILE)   // 49152
#define STAGE_PITCH 132                    // floats; epilogue staging (reuses S/W region)

__device__ float          g_xT[8 * 96 * 96 * 64];   // NHWC fp32 input
__device__ __nv_bfloat16  g_Whi[9 * 64 * 64];       // [tap][oc][ic]
__device__ __nv_bfloat16  g_Wlo[9 * 64 * 64];

// ---------------- helpers ----------------
__device__ __forceinline__ u32 smem_u32(const void* p) {
    u32 a;
    asm("{ .reg .u64 t; cvta.to.shared.u64 t, %1; cvt.u32.u64 %0, t; }" : "=r"(a) : "l"(p));
    return a;
}
__device__ __forceinline__ ull fma2(ull a, ull b, ull c) {
    ull d; asm("fma.rn.f32x2 %0, %1, %2, %3;" : "=l"(d) : "l"(a), "l"(b), "l"(c));
    return d;
}
__device__ __forceinline__ ull pack2(float lo, float hi) {
    ull d; asm("mov.b64 %0, {%1, %2};" : "=l"(d) : "f"(lo), "f"(hi));
    return d;
}
__device__ __forceinline__ void unpack2(ull v, float& lo, float& hi) {
    asm("mov.b64 {%0, %1}, %2;" : "=f"(lo), "=f"(hi) : "l"(v));
}
__device__ __forceinline__ u32 bf16x2_of(float lo, float hi) {   // lo elem in low 16 bits
    u32 r; asm("cvt.rn.bf16x2.f32 %0, %1, %2;" : "=r"(r) : "f"(hi), "f"(lo));
    return r;
}
__device__ __forceinline__ void ldsm4(u32* r, u32 addr) {
    asm volatile("ldmatrix.sync.aligned.m8n8.x4.shared.b16 {%0,%1,%2,%3}, [%4];"
        : "=r"(r[0]), "=r"(r[1]), "=r"(r[2]), "=r"(r[3]) : "r"(addr));
}
__device__ __forceinline__ void mma_bf16(float* d, const u32* a, const u32* b) {
    asm volatile("mma.sync.aligned.m16n8k16.row.col.f32.bf16.bf16.f32 "
        "{%0,%1,%2,%3}, {%4,%5,%6,%7}, {%8,%9}, {%0,%1,%2,%3};"
        : "+f"(d[0]), "+f"(d[1]), "+f"(d[2]), "+f"(d[3])
        : "r"(a[0]), "r"(a[1]), "r"(a[2]), "r"(a[3]), "r"(b[0]), "r"(b[1]));
}

// ---------------------------------------------------------------------------
// NCHW -> NHWC transpose (validated in R4)
// ---------------------------------------------------------------------------
__global__ void transpose_x_kernel(const float* __restrict__ x) {
    __shared__ float tile[32][33];
    int bh = blockIdx.z, c0 = blockIdx.y * 32, w0 = blockIdx.x * 32;
    int b = bh / 96, h = bh - b * 96;
    int tid = threadIdx.x;
    int tx = tid & 31, ty = tid >> 5;
    #pragma unroll
    for (int i = 0; i < 8; i++) {
        int c = ty + 4 * i;
        tile[c][tx] = x[(((size_t)b * 64 + c0 + c) * 96 + h) * 96 + w0 + tx];
    }
    __syncthreads();
    int wi = tid >> 2;
    #pragma unroll
    for (int i = 0; i < 2; i++) {
        int q = (tid & 3) + 4 * i;
        float4 v = make_float4(tile[4 * q][wi], tile[4 * q + 1][wi],
                               tile[4 * q + 2][wi], tile[4 * q + 3][wi]);
        *(float4*)&g_xT[(((size_t)b * 96 + h) * 96 + (w0 + wi)) * 64 + c0 + 4 * q] = v;
    }
}

// weight[oc][ic][tap] -> g_Whi/g_Wlo [tap][oc][ic] (bf16 hi/lo split)
__global__ void prep_w_kernel(const float* __restrict__ w) {
    int o = blockIdx.x * 256 + threadIdx.x;
    if (o < 9 * 64 * 64) {
        int k = o >> 12, oc = (o >> 6) & 63, ic = o & 63;
        float v = w[(oc * 64 + ic) * 9 + k];
        __nv_bfloat16 h = __float2bfloat16(v);
        g_Whi[o] = h;
        g_Wlo[o] = __float2bfloat16(v - __bfloat162float(h));
    }
}

// ---------------------------------------------------------------------------
// Main kernel: block = 128 px x 64 oc, 128 threads (4 warps).
// Per tap: sample bilinear -> bf16 hi/lo S-planes + stage W hi/lo;
// then 12 k-steps of m16n8k16 bf16 mma (3-term split), acc in registers.
// ---------------------------------------------------------------------------
__global__ __launch_bounds__(128, 3) void deform_main_kernel(
    const float* __restrict__ off,
    const float* __restrict__ x2,
    const float* __restrict__ bias,
    float* __restrict__ out)
{
    extern __shared__ char smem[];
    const u32 smem_u = smem_u32(smem);

    const int tid  = threadIdx.x;
    const int lane = tid & 31;
    const int wid  = tid >> 5;
    const int l16  = lane & 15;
    const int half = lane >> 4;

    const int blk = blockIdx.x;
    const int b   = blk / 72;
    const int pb  = (blk - b * 72) * 128;

    const float* xTb  = g_xT + (size_t)b * (HW * 64);
    const float* offb = off + (size_t)b * (18 * HW);

    float acc[2][8][4];
    #pragma unroll
    for (int mi = 0; mi < 2; mi++)
        #pragma unroll
        for (int nj = 0; nj < 8; nj++)
            #pragma unroll
            for (int q = 0; q < 4; q++) acc[mi][nj][q] = 0.0f;

    // per-lane ldmatrix addressing constants
    const int g  = lane >> 3;
    const int r8 = lane & 7;
    // A: matrix g -> rows (g&1)*8 + r8 (+ mi*16 + wid*32), k-half (g>>1)
    int arow0 = wid * 32 + (g & 1) * 8 + r8;           // mi=0
    u32 aRb[2], aXm[2];
    #pragma unroll
    for (int mi = 0; mi < 2; mi++) {
        int row = arow0 + mi * 16;
        aRb[mi] = (u32)row * 128;
        aXm[mi] = (u32)(row & 7) << 4;
    }
    const u32 aCb = (u32)(g >> 1) * 16;                // k-half byte offset
    // B: matrix g -> row (g>>1)*8 + r8 (+ njp*16), k-half (g&1)
    const int brow0 = (g >> 1) * 8 + r8;
    const u32 bRb = (u32)brow0 * 128;
    const u32 bXm = (u32)(brow0 & 7) << 4;
    const u32 bCb = (u32)(g & 1) * 16;

    // ---- stage weight tile (hi+lo) for tap k ----
    auto loadW = [&](int k) {
        u32 wh = smem_u + SM_WHI;
        const uint4* sh = (const uint4*)(g_Whi + k * 4096);
        const uint4* sl = (const uint4*)(g_Wlo + k * 4096);
        #pragma unroll
        for (int i = 0; i < 4; i++) {
            int e = tid + 128 * i;                 // 16B chunk 0..511
            u32 o = (u32)e * 16;
            u32 sw = o ^ ((o >> 3) & 0x70);
            uint4 vh = sh[e], vl = sl[e];
            asm volatile("st.shared.v4.b32 [%0], {%1,%2,%3,%4};" ::
                "r"(wh + sw), "r"(vh.x), "r"(vh.y), "r"(vh.z), "r"(vh.w) : "memory");
            asm volatile("st.shared.v4.b32 [%0], {%1,%2,%3,%4};" ::
                "r"(wh + W_TILE + sw), "r"(vl.x), "r"(vl.y), "r"(vl.z), "r"(vl.w) : "memory");
        }
    };

    // ---- sample tap k into S hi/lo planes ----
    auto sample = [&](int k) {
        u32 sh = smem_u + SM_SHI;
        u32 sl = smem_u + SM_SLO;
        int ki = k / 3, kj = k - ki * 3;
        const float* offy = offb + (size_t)(2 * k) * HW;
        const float* offx = offy + HW;
        #pragma unroll 2
        for (int it = 0; it < 16; it++) {
            int t = (wid * 16 + it) * 2 + half;     // px row 0..127
            int p = pb + t;
            int ho = p / 96;
            int wo = p - ho * 96;

            float oy = __ldg(offy + p);
            float ox = __ldg(offx + p);
            float y = (float)(ho - 1 + ki) + oy;
            float x = (float)(wo - 1 + kj) + ox;

            float y0f = floorf(y), x0f = floorf(x);
            float wy1 = y - y0f, wx1 = x - x0f;
            float wy0 = 1.0f - wy1, wx0 = 1.0f - wx1;
            int y0 = (int)y0f, x0 = (int)x0f;

            bool vy0 = (y0 >= 0) && (y0 <= 95);
            bool vy1 = (y0 >= -1) && (y0 <= 94);
            bool vx0 = (x0 >= 0) && (x0 <= 95);
            bool vx1 = (x0 >= -1) && (x0 <= 94);
            int yc0 = min(max(y0, 0), 95), yc1 = min(max(y0 + 1, 0), 95);
            int xc0 = min(max(x0, 0), 95), xc1 = min(max(x0 + 1, 0), 95);

            float w00 = (vy0 && vx0) ? wy0 * wx0 : 0.0f;
            float w01 = (vy0 && vx1) ? wy0 * wx1 : 0.0f;
            float w10 = (vy1 && vx0) ? wy1 * wx0 : 0.0f;
            float w11 = (vy1 && vx1) ? wy1 * wx1 : 0.0f;

            float4 v00 = ((const float4*)(xTb + ((size_t)(yc0 * 96 + xc0) << 6)))[l16];
            float4 v01 = ((const float4*)(xTb + ((size_t)(yc0 * 96 + xc1) << 6)))[l16];
            float4 v10 = ((const float4*)(xTb + ((size_t)(yc1 * 96 + xc0) << 6)))[l16];
            float4 v11 = ((const float4*)(xTb + ((size_t)(yc1 * 96 + xc1) << 6)))[l16];

            ull W00 = pack2(w00, w00), W01 = pack2(w01, w01);
            ull W10 = pack2(w10, w10), W11 = pack2(w11, w11);
            ull a0 = fma2(W00, pack2(v00.x, v00.y),
                     fma2(W01, pack2(v01.x, v01.y),
                     fma2(W10, pack2(v10.x, v10.y),
                     fma2(W11, pack2(v11.x, v11.y), 0ULL))));
            ull a1 = fma2(W00, pack2(v00.z, v00.w),
                     fma2(W01, pack2(v01.z, v01.w),
                     fma2(W10, pack2(v10.z, v10.w),
                     fma2(W11, pack2(v11.z, v11.w), 0ULL))));

            float s0, s1, s2, s3;
            unpack2(a0, s0, s1);
            unpack2(a1, s2, s3);

            u32 h01 = bf16x2_of(s0, s1);
            u32 h23 = bf16x2_of(s2, s3);
            float hf0 = __uint_as_float(h01 << 16);
            float hf1 = __uint_as_float(h01 & 0xFFFF0000u);
            float hf2 = __uint_as_float(h23 << 16);
            float hf3 = __uint_as_float(h23 & 0xFFFF0000u);
            u32 l01 = bf16x2_of(s0 - hf0, s1 - hf1);
            u32 l23 = bf16x2_of(s2 - hf2, s3 - hf3);

            u32 o = (u32)t * 128 + (u32)l16 * 8;
            u32 sw = o ^ ((o >> 3) & 0x70);
            asm volatile("st.shared.v2.b32 [%0], {%1,%2};" ::
                "r"(sh + sw), "r"(h01), "r"(h23) : "memory");
            asm volatile("st.shared.v2.b32 [%0], {%1,%2};" ::
                "r"(sl + sw), "r"(l01), "r"(l23) : "memory");
        }
    };

    // ---- 9 taps: sample -> 3-term bf16 MMA ----
    for (int k = 0; k < 9; k++) {
        loadW(k);
        sample(k);
        __syncthreads();

        #pragma unroll
        for (int pass = 0; pass < 3; pass++) {
            u32 Ab = smem_u + (pass == 2 ? SM_SLO : SM_SHI);
            u32 Bb = smem_u + (pass == 1 ? SM_WLO : SM_WHI);
            #pragma unroll
            for (int k0 = 0; k0 < 4; k0++) {
                u32 cb0 = (u32)k0 * 32;
                u32 afr[2][4];
                #pragma unroll
                for (int mi = 0; mi < 2; mi++)
                    ldsm4(afr[mi], Ab + aRb[mi] + ((cb0 + aCb) ^ aXm[mi]));
                #pragma unroll
                for (int njp = 0; njp < 4; njp++) {
                    u32 bfr[4];
                    ldsm4(bfr, Bb + bRb + (u32)njp * 2048 + ((cb0 + bCb) ^ bXm));
                    mma_bf16(acc[0][2 * njp],     afr[0], bfr);
                    mma_bf16(acc[1][2 * njp],     afr[1], bfr);
                    mma_bf16(acc[0][2 * njp + 1], afr[0], bfr + 2);
                    mma_bf16(acc[1][2 * njp + 1], afr[1], bfr + 2);
                }
            }
        }
        __syncthreads();
    }

    // ---- epilogue: fragment -> smem transpose -> coalesced NCHW stores ----
    float* stage = (float*)smem;    // [64 oc][STAGE_PITCH]
    #pragma unroll
    for (int mi = 0; mi < 2; mi++) {
        int row0 = wid * 32 + mi * 16 + (lane >> 2);
        #pragma unroll
        for (int nj = 0; nj < 8; nj++) {
            int oc = nj * 8 + 2 * (lane & 3);
            stage[oc * STAGE_PITCH + row0]           = acc[mi][nj][0];
            stage[(oc + 1) * STAGE_PITCH + row0]     = acc[mi][nj][1];
            stage[oc * STAGE_PITCH + row0 + 8]       = acc[mi][nj][2];
            stage[(oc + 1) * STAGE_PITCH + row0 + 8] = acc[mi][nj][3];
        }
    }
    __syncthreads();

    const int p = pb + tid;
    #pragma unroll 8
    for (int oc = 0; oc < 64; oc++) {
        size_t idx = ((size_t)(b * 64 + oc)) * HW + p;
        float v = stage[oc * STAGE_PITCH + tid] + __ldg(bias + oc) + __ldg(x2 + idx);
        out[idx] = fminf(fmaxf(v, 0.0f), 6.0f);
    }
}

extern "C" void kernel_launch(void* const* d_in, const int* in_sizes, int n_in,
                              void* d_out, int out_size) {
    const float* x      = (const float*)d_in[0];
    const float* offset = (const float*)d_in[1];
    const float* x2     = (const float*)d_in[2];
    const float* weight = (const float*)d_in[3];
    const float* bias   = (const float*)d_in[4];
    float* out = (float*)d_out;
    (void)in_sizes; (void)n_in; (void)out_size;

    cudaFuncSetAttribute(deform_main_kernel,
                         cudaFuncAttributeMaxDynamicSharedMemorySize, SMEM_BYTES);

    transpose_x_kernel<<<dim3(3, 2, 768), 128>>>(x);
    prep_w_kernel<<<144, 256>>>(weight);
    deform_main_kernel<<<576, 128, SMEM_BYTES>>>(offset, x2, bias, out);
}